// round 8
// baseline (speedup 1.0000x reference)
#include <cuda_runtime.h>
#include <cstdint>
#include <cub/cub.cuh>

// ---------------------------------------------------------------------------
// AUCShuffled — R6: grouped pipeline to hide sorts under threefry ALU.
//   64 batches -> 8 groups x 8 batches (2.1M elem/group).
//   s1 (ALU): keygen; per group: gen1, gen2 (exact jax threefry; 20 rounds)
//   s0 (DRAM): per group (event-gated): sortB pairs -> sortC pairs ->
//              combine(labels) -> final keys-only sort -> rank-sum reduce
// Bit budget (lesson from R5: shuffle-key ties are ~100x worse than pred ties):
//   perm sorts : 3 batch | 21 rand          -> 24-bit, 3 passes, err ~5e-5
//   final sort : 3 batch | 17 pred | label  -> 21-bit, 3 passes, err ~1e-8
// ---------------------------------------------------------------------------

#define NB    64
#define NPB   262144              // 1<<18 per batch
#define HALF  131072
#define NTOT  (NB * NPB)          // 16777216
#define G     8                   // groups
#define BPG   (NB / G)            // 8 batches per group
#define GRP   (BPG * NPB)         // 2097152 elements per group

// ---------------- static device scratch ------------------------------------
__device__ unsigned int       g_kB0[NTOT];   // perm sortB keys / final keys
__device__ unsigned int       g_kB1[NTOT];
__device__ unsigned int       g_kC0[NTOT];   // perm sortC keys
__device__ unsigned int       g_kC1[NTOT];
__device__ unsigned int       g_v0 [NTOT];   // payload double buffer
__device__ unsigned int       g_v1 [NTOT];
__device__ unsigned int       g_subkeys[NB * 4];
__device__ unsigned long long g_sum[NB];
__device__ unsigned int       g_cnt[NB];
__device__ unsigned char      g_temp[64u * 1024u * 1024u];

// ---------------- threefry2x32 (Random123 / jax, 20 rounds; R2-exact) -------
__device__ __forceinline__ void tf2x32(unsigned k0, unsigned k1,
                                       unsigned x0, unsigned x1,
                                       unsigned& o0, unsigned& o1) {
    unsigned ks2 = 0x1BD11BDAu ^ k0 ^ k1;
    x0 += k0; x1 += k1;
#define TF_RND(r) { x0 += x1; x1 = __funnelshift_l(x1, x1, (r)); x1 ^= x0; }
    TF_RND(13) TF_RND(15) TF_RND(26) TF_RND(6)   x0 += k1;  x1 += ks2 + 1u;
    TF_RND(17) TF_RND(29) TF_RND(16) TF_RND(24)  x0 += ks2; x1 += k0  + 2u;
    TF_RND(13) TF_RND(15) TF_RND(26) TF_RND(6)   x0 += k0;  x1 += k1  + 3u;
    TF_RND(17) TF_RND(29) TF_RND(16) TF_RND(24)  x0 += k1;  x1 += ks2 + 4u;
    TF_RND(13) TF_RND(15) TF_RND(26) TF_RND(6)   x0 += ks2; x1 += k0  + 5u;
#undef TF_RND
    o0 = x0; o1 = x1;
}

__device__ __forceinline__ unsigned f2u(float f) {
    unsigned u = __float_as_uint(f);
    return (u & 0x80000000u) ? ~u : (u | 0x80000000u);
}

// ---------------- key derivation -------------------------------------------
__global__ void keygen_kernel() {
    int b = threadIdx.x;                       // 64 threads
    g_sum[b] = 0ull; g_cnt[b] = 0u;
    unsigned kb0, kb1;
    tf2x32(0u, 42u, 0u, (unsigned)b, kb0, kb1);
    unsigned nk0, nk1, s10, s11, s20, s21;
    tf2x32(kb0, kb1, 0u, 0u, nk0, nk1);
    tf2x32(kb0, kb1, 0u, 1u, s10, s11);
    tf2x32(nk0, nk1, 0u, 1u, s20, s21);
    g_subkeys[4*b+0] = s10; g_subkeys[4*b+1] = s11;
    g_subkeys[4*b+2] = s20; g_subkeys[4*b+3] = s21;
}

// ---------------- per-group threefry keygen (ALU-bound, stream s1) ----------
// round-1: keys into g_kB0 slice + payload (pred composite) into g_v0 slice
__global__ void gen1_kernel(int g, const float* __restrict__ pred) {
    int idx = blockIdx.x * 256 + threadIdx.x;  // [0, BPG*HALF)
    int bIn = idx >> 17;
    unsigned i = (unsigned)(idx & (HALF - 1));
    int b = g * BPG + bIn;
    unsigned k0 = g_subkeys[4*b + 0], k1 = g_subkeys[4*b + 1];
    unsigned a0, a1, u, v;
    tf2x32(k0, k1, 0u, i,                  a0, a1); u = a0 ^ a1;
    tf2x32(k0, k1, 0u, (unsigned)HALF + i, a0, a1); v = a0 ^ a1;
    size_t base = ((size_t)g * GRP) + ((size_t)bIn << 18) + i;
    unsigned hb = (unsigned)bIn << 21;         // 3 batch bits over 21 rand bits
    g_kB0[base]        = hb | (u >> 11);
    g_kB0[base + HALF] = hb | (v >> 11);
    unsigned pb = (unsigned)bIn << 18;         // payload: bIn|pred17|label-slot
    g_v0[base]        = pb | ((f2u(pred[base])        >> 15) << 1);
    g_v0[base + HALF] = pb | ((f2u(pred[base + HALF]) >> 15) << 1);
}

// round-2: keys (indexed by post-round-1 position) into g_kC0 slice
__global__ void gen2_kernel(int g) {
    int idx = blockIdx.x * 256 + threadIdx.x;
    int bIn = idx >> 17;
    unsigned i = (unsigned)(idx & (HALF - 1));
    int b = g * BPG + bIn;
    unsigned k0 = g_subkeys[4*b + 2], k1 = g_subkeys[4*b + 3];
    unsigned a0, a1, u, v;
    tf2x32(k0, k1, 0u, i,                  a0, a1); u = a0 ^ a1;
    tf2x32(k0, k1, 0u, (unsigned)HALF + i, a0, a1); v = a0 ^ a1;
    size_t base = ((size_t)g * GRP) + ((size_t)bIn << 18) + i;
    unsigned hb = (unsigned)bIn << 21;
    g_kC0[base]        = hb | (u >> 11);
    g_kC0[base + HALF] = hb | (v >> 11);
}

// ---------------- combine: attach label at final position, count n+ ---------
__global__ void combine_kernel(int g, const int* __restrict__ tmap,
                               const unsigned int* __restrict__ vfin) {
    int j = blockIdx.x * 256 + threadIdx.x;    // [0, GRP)
    size_t gj = (size_t)g * GRP + j;
    unsigned u = (tmap[gj] > 0) ? 1u : 0u;
    g_kB0[gj] = vfin[j] | u;                   // kB slice dead after sortB
    unsigned c = u;
    for (int o = 16; o; o >>= 1) c += __shfl_down_sync(0xffffffffu, c, o);
    __shared__ unsigned sc[8];
    int w = threadIdx.x >> 5;
    if ((threadIdx.x & 31) == 0) sc[w] = c;
    __syncthreads();
    if (threadIdx.x == 0) {
        unsigned C = 0;
        #pragma unroll
        for (int k = 0; k < 8; k++) C += sc[k];
        atomicAdd(&g_cnt[gj >> 18], C);
    }
}

// ---------------- rank-sum over final per-group sorted keys ------------------
__global__ void reduce_kernel(int g, const unsigned int* __restrict__ keys) {
    int j = blockIdx.x * 256 + threadIdx.x;    // [0, GRP)
    size_t gj = (size_t)g * GRP + j;
    unsigned k = keys[j];
    unsigned long long s =
        (k & 1u) ? (unsigned long long)((unsigned)(gj & (NPB - 1)) + 1u) : 0ull;
    for (int o = 16; o; o >>= 1) s += __shfl_down_sync(0xffffffffu, s, o);
    __shared__ unsigned long long ss[8];
    int w = threadIdx.x >> 5;
    if ((threadIdx.x & 31) == 0) ss[w] = s;
    __syncthreads();
    if (threadIdx.x == 0) {
        unsigned long long S = 0;
        #pragma unroll
        for (int kk = 0; kk < 8; kk++) S += ss[kk];
        atomicAdd(&g_sum[gj >> 18], S);
    }
}

__global__ void finalize_kernel(float* __restrict__ out) {
    int b = threadIdx.x;                       // 64 threads
    double np = (double)g_cnt[b];
    double nn = (double)NPB - np;
    double auc = ((double)g_sum[b] - np * (np + 1.0) * 0.5) / (np * nn);
    for (int o = 16; o; o >>= 1)
        auc += __shfl_down_sync(0xffffffffu, auc, o);
    __shared__ double sh[2];
    if ((b & 31) == 0) sh[b >> 5] = auc;
    __syncthreads();
    if (b == 0) out[0] = (float)((sh[0] + sh[1]) * (1.0 / 64.0));
}

// ---------------------------------------------------------------------------
extern "C" void kernel_launch(void* const* d_in, const int* in_sizes, int n_in,
                              void* d_out, int out_size) {
    const float* pred = (const float*)d_in[0];
    const int*   tmap = (const int*)d_in[1];
    float*       out  = (float*)d_out;

    static cudaStream_t s1 = nullptr;
    static cudaEvent_t  evF = nullptr, e1[G], e2[G];
    if (!s1) {
        cudaStreamCreateWithFlags(&s1, cudaStreamNonBlocking);
        cudaEventCreateWithFlags(&evF, cudaEventDisableTiming);
        for (int g = 0; g < G; g++) {
            cudaEventCreateWithFlags(&e1[g], cudaEventDisableTiming);
            cudaEventCreateWithFlags(&e2[g], cudaEventDisableTiming);
        }
    }

    void *pkB0, *pkB1, *pkC0, *pkC1, *pv0, *pv1, *ptmp;
    cudaGetSymbolAddress(&pkB0, g_kB0);
    cudaGetSymbolAddress(&pkB1, g_kB1);
    cudaGetSymbolAddress(&pkC0, g_kC0);
    cudaGetSymbolAddress(&pkC1, g_kC1);
    cudaGetSymbolAddress(&pv0,  g_v0);
    cudaGetSymbolAddress(&pv1,  g_v1);
    cudaGetSymbolAddress(&ptmp, g_temp);
    unsigned *kB0 = (unsigned*)pkB0, *kB1 = (unsigned*)pkB1;
    unsigned *kC0 = (unsigned*)pkC0, *kC1 = (unsigned*)pkC1;
    unsigned *v0  = (unsigned*)pv0,  *v1  = (unsigned*)pv1;

    {   // temp-size sanity (onesweep metadata only; shared, s0-serialized)
        size_t need = 0;
        cub::DoubleBuffer<unsigned> k(kB0, kB1), v(v0, v1);
        cub::DeviceRadixSort::SortPairs(nullptr, need, k, v, GRP, 0, 24,
                                        (cudaStream_t)0);
        if (need > sizeof(g_temp)) return;
    }
    size_t temp_bytes = sizeof(g_temp);

    const int GGEN = (BPG * HALF) / 256;       // 4096 blocks
    const int GSTR = GRP / 256;                // 8192 blocks

    // ---- fork ALU stream -------------------------------------------------
    cudaEventRecord(evF, (cudaStream_t)0);
    cudaStreamWaitEvent(s1, evF, 0);

    keygen_kernel<<<1, 64, 0, s1>>>();
    for (int g = 0; g < G; g++) {
        gen1_kernel<<<GGEN, 256, 0, s1>>>(g, pred);
        cudaEventRecord(e1[g], s1);
        gen2_kernel<<<GGEN, 256, 0, s1>>>(g);
        cudaEventRecord(e2[g], s1);
    }

    // ---- DRAM stream: per-group sort pipeline ----------------------------
    for (int g = 0; g < G; g++) {
        size_t off = (size_t)g * GRP;

        cudaStreamWaitEvent((cudaStream_t)0, e1[g], 0);
        cub::DoubleBuffer<unsigned> kB(kB0 + off, kB1 + off);
        cub::DoubleBuffer<unsigned> vB(v0 + off, v1 + off);
        cub::DeviceRadixSort::SortPairs(ptmp, temp_bytes, kB, vB, GRP, 0, 24,
                                        (cudaStream_t)0);

        cudaStreamWaitEvent((cudaStream_t)0, e2[g], 0);
        cub::DoubleBuffer<unsigned> kC(kC0 + off, kC1 + off);
        cub::DoubleBuffer<unsigned> vC(vB.Current(), vB.Alternate());
        cub::DeviceRadixSort::SortPairs(ptmp, temp_bytes, kC, vC, GRP, 0, 24,
                                        (cudaStream_t)0);

        combine_kernel<<<GSTR, 256>>>(g, tmap, vC.Current());

        cub::DoubleBuffer<unsigned> kF(kB0 + off, kB1 + off);
        cub::DeviceRadixSort::SortKeys(ptmp, temp_bytes, kF, GRP, 0, 21,
                                       (cudaStream_t)0);

        reduce_kernel<<<GSTR, 256>>>(g, kF.Current());
    }

    finalize_kernel<<<1, 64>>>(out);
}

// round 9
// speedup vs baseline: 1.2250x; 1.2250x over previous
#include <cuda_runtime.h>
#include <cstdint>
#include <cub/cub.cuh>

// ---------------------------------------------------------------------------
// AUCShuffled — R9: two concurrent sort pipelines + rank-LUT (no third sort).
//   s0 : keygen -> pred histogram -> global exclusive scan -> avg-rank LUT
//   s1 : half 0: gen(both rounds) -> sortB -> sortC -> LUT-reduce
//   s2 : half 1: same
//   s0 : join -> finalize
// Sort keys 32-bit = 5 batch | 27 random (4 passes; 27-bit keys are in the
// R4-proven error regime ~1e-5). Ranks via per-batch average-rank LUT
// (rank2 = 2*lo + c + 1) — exactly the reference's (lo+hi+1) tie handling.
// ---------------------------------------------------------------------------

#define NB    64
#define NPB   262144              // 1<<18
#define HALF  131072
#define NTOT  (NB * NPB)          // 16777216
#define HB    32                  // batches per half
#define HN    (HB * NPB)          // 8388608 per half
#define PBITS 17
#define NBINS (NB << PBITS)       // 8388608 rank-LUT bins

// ---------------- static device scratch ------------------------------------
__device__ unsigned int       g_kB0[NTOT], g_kB1[NTOT];   // round-1 keys
__device__ unsigned int       g_kC0[NTOT], g_kC1[NTOT];   // round-2 keys
__device__ unsigned int       g_v0 [NTOT], g_v1 [NTOT];   // pred17 payload
__device__ unsigned int       g_hist[NBINS];              // hist -> rank2 LUT
__device__ unsigned int       g_scan[NBINS];              // exclusive scan
__device__ unsigned int       g_subkeys[NB * 4];
__device__ unsigned long long g_sum[NB];
__device__ unsigned int       g_cnt[NB];
__device__ unsigned char      g_tempA[48u << 20];
__device__ unsigned char      g_tempB[48u << 20];
__device__ unsigned char      g_tempS[16u << 20];

// ---------------- threefry2x32 (Random123 / jax, 20 rounds; R2-exact) -------
__device__ __forceinline__ void tf2x32(unsigned k0, unsigned k1,
                                       unsigned x0, unsigned x1,
                                       unsigned& o0, unsigned& o1) {
    unsigned ks2 = 0x1BD11BDAu ^ k0 ^ k1;
    x0 += k0; x1 += k1;
#define TF_RND(r) { x0 += x1; x1 = __funnelshift_l(x1, x1, (r)); x1 ^= x0; }
    TF_RND(13) TF_RND(15) TF_RND(26) TF_RND(6)   x0 += k1;  x1 += ks2 + 1u;
    TF_RND(17) TF_RND(29) TF_RND(16) TF_RND(24)  x0 += ks2; x1 += k0  + 2u;
    TF_RND(13) TF_RND(15) TF_RND(26) TF_RND(6)   x0 += k0;  x1 += k1  + 3u;
    TF_RND(17) TF_RND(29) TF_RND(16) TF_RND(24)  x0 += k1;  x1 += ks2 + 4u;
    TF_RND(13) TF_RND(15) TF_RND(26) TF_RND(6)   x0 += ks2; x1 += k0  + 5u;
#undef TF_RND
    o0 = x0; o1 = x1;
}

__device__ __forceinline__ unsigned f2u(float f) {
    unsigned u = __float_as_uint(f);
    return (u & 0x80000000u) ? ~u : (u | 0x80000000u);
}

// ---------------- key derivation -------------------------------------------
__global__ void keygen_kernel() {
    int b = threadIdx.x;                        // 64 threads
    g_sum[b] = 0ull; g_cnt[b] = 0u;
    unsigned kb0, kb1;
    tf2x32(0u, 42u, 0u, (unsigned)b, kb0, kb1);
    unsigned nk0, nk1, s10, s11, s20, s21;
    tf2x32(kb0, kb1, 0u, 0u, nk0, nk1);
    tf2x32(kb0, kb1, 0u, 1u, s10, s11);
    tf2x32(nk0, nk1, 0u, 1u, s20, s21);
    g_subkeys[4*b+0] = s10; g_subkeys[4*b+1] = s11;
    g_subkeys[4*b+2] = s20; g_subkeys[4*b+3] = s21;
}

// ---------------- fused per-half keygen: both shuffle rounds + payload ------
__global__ void gen_kernel(int h, const float* __restrict__ pred) {
    int idx = blockIdx.x * 256 + threadIdx.x;   // [0, HB*HALF) = 4.2M
    int bIn = idx >> 17;
    unsigned i = (unsigned)(idx & (HALF - 1));
    int b = h * HB + bIn;
    unsigned k10 = g_subkeys[4*b+0], k11 = g_subkeys[4*b+1];
    unsigned k20 = g_subkeys[4*b+2], k21 = g_subkeys[4*b+3];
    unsigned a0, a1, u1, w1, u2, w2;
    tf2x32(k10, k11, 0u, i,                  a0, a1); u1 = a0 ^ a1;
    tf2x32(k10, k11, 0u, (unsigned)HALF + i, a0, a1); w1 = a0 ^ a1;
    tf2x32(k20, k21, 0u, i,                  a0, a1); u2 = a0 ^ a1;
    tf2x32(k20, k21, 0u, (unsigned)HALF + i, a0, a1); w2 = a0 ^ a1;
    size_t base = ((size_t)h * HN) + ((size_t)bIn << 18) + i;
    unsigned hb = (unsigned)bIn << 27;          // 5 batch bits | 27 random
    g_kB0[base]        = hb | (u1 >> 5);
    g_kB0[base + HALF] = hb | (w1 >> 5);
    g_kC0[base]        = hb | (u2 >> 5);
    g_kC0[base + HALF] = hb | (w2 >> 5);
    g_v0[base]         = f2u(pred[base])        >> (32 - PBITS);
    g_v0[base + HALF]  = f2u(pred[base + HALF]) >> (32 - PBITS);
}

// ---------------- rank LUT path (stream 0, overlapped) -----------------------
__global__ void histz_kernel() {
    int i = blockIdx.x * 256 + threadIdx.x;
    g_hist[i] = 0u;
}

__global__ void hist_kernel(const float* __restrict__ pred) {
    int g = blockIdx.x * 256 + threadIdx.x;     // [0, NTOT)
    int b = g >> 18;
    unsigned k = f2u(pred[g]) >> (32 - PBITS);
    atomicAdd(&g_hist[((unsigned)b << PBITS) | k], 1u);
}

// rank2[bin] = 2*lo_local + c + 1 = E[bin] + E[bin+1] - 2*b*NPB + 1
// (valid across batch boundaries: each batch holds exactly NPB elements)
__global__ void lut_kernel() {
    int i = blockIdx.x * 256 + threadIdx.x;     // [0, NBINS)
    unsigned E  = g_scan[i];
    unsigned En = (i + 1 < NBINS) ? g_scan[i + 1] : (unsigned)NTOT;
    unsigned b  = (unsigned)(i >> PBITS);
    g_hist[i] = E + En - 2u * b * (unsigned)NPB + 1u;
}

// ---------------- final reduce: sum rank2 over positives ---------------------
__global__ void reduce_kernel(int h, const unsigned int* __restrict__ pay,
                              const int* __restrict__ tmap) {
    int j = blockIdx.x * 256 + threadIdx.x;     // [0, HN)
    size_t gj = (size_t)h * HN + j;
    int b = (int)(gj >> 18);                    // constant per block
    unsigned long long s = 0ull; unsigned c = 0u;
    if (tmap[gj] > 0) {
        s = (unsigned long long)g_hist[((unsigned)b << PBITS) | pay[j]];
        c = 1u;
    }
    for (int o = 16; o; o >>= 1) {
        s += __shfl_down_sync(0xffffffffu, s, o);
        c += __shfl_down_sync(0xffffffffu, c, o);
    }
    __shared__ unsigned long long ss[8];
    __shared__ unsigned int      sc[8];
    int w = threadIdx.x >> 5;
    if ((threadIdx.x & 31) == 0) { ss[w] = s; sc[w] = c; }
    __syncthreads();
    if (threadIdx.x == 0) {
        unsigned long long S = 0; unsigned C = 0;
        #pragma unroll
        for (int k = 0; k < 8; k++) { S += ss[k]; C += sc[k]; }
        atomicAdd(&g_sum[b], S);
        atomicAdd(&g_cnt[b], C);
    }
}

__global__ void finalize_kernel(float* __restrict__ out) {
    int b = threadIdx.x;                        // 64 threads
    double np = (double)g_cnt[b];
    double nn = (double)NPB - np;
    double sumRanks = 0.5 * (double)g_sum[b];   // rank2 = 2*rank
    double auc = (sumRanks - np * (np + 1.0) * 0.5) / (np * nn);
    for (int o = 16; o; o >>= 1)
        auc += __shfl_down_sync(0xffffffffu, auc, o);
    __shared__ double sh[2];
    if ((b & 31) == 0) sh[b >> 5] = auc;
    __syncthreads();
    if (b == 0) out[0] = (float)((sh[0] + sh[1]) * (1.0 / 64.0));
}

// ---------------------------------------------------------------------------
extern "C" void kernel_launch(void* const* d_in, const int* in_sizes, int n_in,
                              void* d_out, int out_size) {
    const float* pred = (const float*)d_in[0];
    const int*   tmap = (const int*)d_in[1];
    float*       out  = (float*)d_out;

    static cudaStream_t s1 = nullptr, s2 = nullptr;
    static cudaEvent_t  evK = nullptr, evLUT = nullptr, evR1 = nullptr,
                        evR2 = nullptr;
    if (!s1) {
        cudaStreamCreateWithFlags(&s1, cudaStreamNonBlocking);
        cudaStreamCreateWithFlags(&s2, cudaStreamNonBlocking);
        cudaEventCreateWithFlags(&evK,  cudaEventDisableTiming);
        cudaEventCreateWithFlags(&evLUT, cudaEventDisableTiming);
        cudaEventCreateWithFlags(&evR1, cudaEventDisableTiming);
        cudaEventCreateWithFlags(&evR2, cudaEventDisableTiming);
    }

    void *pkB0, *pkB1, *pkC0, *pkC1, *pv0, *pv1, *phist, *pscan;
    void *ptA, *ptB, *ptS;
    cudaGetSymbolAddress(&pkB0, g_kB0);  cudaGetSymbolAddress(&pkB1, g_kB1);
    cudaGetSymbolAddress(&pkC0, g_kC0);  cudaGetSymbolAddress(&pkC1, g_kC1);
    cudaGetSymbolAddress(&pv0,  g_v0);   cudaGetSymbolAddress(&pv1,  g_v1);
    cudaGetSymbolAddress(&phist, g_hist);
    cudaGetSymbolAddress(&pscan, g_scan);
    cudaGetSymbolAddress(&ptA, g_tempA); cudaGetSymbolAddress(&ptB, g_tempB);
    cudaGetSymbolAddress(&ptS, g_tempS);
    unsigned *kB0 = (unsigned*)pkB0, *kB1 = (unsigned*)pkB1;
    unsigned *kC0 = (unsigned*)pkC0, *kC1 = (unsigned*)pkC1;
    unsigned *v0  = (unsigned*)pv0,  *v1  = (unsigned*)pv1;
    unsigned *hist = (unsigned*)phist, *scan = (unsigned*)pscan;

    {   // temp-size sanity
        size_t need = 0;
        cub::DoubleBuffer<unsigned> k(kB0, kB1), v(v0, v1);
        cub::DeviceRadixSort::SortPairs(nullptr, need, k, v, HN, 0, 32,
                                        (cudaStream_t)0);
        if (need > sizeof(g_tempA)) return;
        need = 0;
        cub::DeviceScan::ExclusiveSum(nullptr, need, hist, scan, NBINS,
                                      (cudaStream_t)0);
        if (need > sizeof(g_tempS)) return;
    }
    size_t tbytesA = sizeof(g_tempA), tbytesB = sizeof(g_tempB);
    size_t tbytesS = sizeof(g_tempS);

    const int GGEN = (HB * HALF) / 256;         // 16384 blocks
    const int GTOT = NTOT / 256;                // 65536
    const int GBIN = NBINS / 256;               // 32768
    const int GHN  = HN / 256;                  // 32768

    // ---- s0: keygen, then rank-LUT path -----------------------------------
    keygen_kernel<<<1, 64>>>();
    cudaEventRecord(evK, (cudaStream_t)0);

    histz_kernel<<<GBIN, 256>>>();
    hist_kernel<<<GTOT, 256>>>(pred);
    cub::DeviceScan::ExclusiveSum(ptS, tbytesS, hist, scan, NBINS,
                                  (cudaStream_t)0);
    lut_kernel<<<GBIN, 256>>>();
    cudaEventRecord(evLUT, (cudaStream_t)0);

    // ---- s1 / s2: per-half shuffle pipelines ------------------------------
    for (int h = 0; h < 2; h++) {
        cudaStream_t sh = (h == 0) ? s1 : s2;
        void* tp        = (h == 0) ? ptA : ptB;
        size_t tb       = (h == 0) ? tbytesA : tbytesB;
        size_t off = (size_t)h * HN;

        cudaStreamWaitEvent(sh, evK, 0);
        gen_kernel<<<GGEN, 256, 0, sh>>>(h, pred);

        cub::DoubleBuffer<unsigned> kB(kB0 + off, kB1 + off);
        cub::DoubleBuffer<unsigned> vB(v0 + off, v1 + off);
        cub::DeviceRadixSort::SortPairs(tp, tb, kB, vB, HN, 0, 32, sh);

        cub::DoubleBuffer<unsigned> kC(kC0 + off, kC1 + off);
        cub::DoubleBuffer<unsigned> vC(vB.Current(), vB.Alternate());
        cub::DeviceRadixSort::SortPairs(tp, tb, kC, vC, HN, 0, 32, sh);

        cudaStreamWaitEvent(sh, evLUT, 0);
        reduce_kernel<<<GHN, 256, 0, sh>>>(h, vC.Current(), tmap);
        cudaEventRecord((h == 0) ? evR1 : evR2, sh);
    }

    // ---- join + finalize ---------------------------------------------------
    cudaStreamWaitEvent((cudaStream_t)0, evR1, 0);
    cudaStreamWaitEvent((cudaStream_t)0, evR2, 0);
    finalize_kernel<<<1, 64>>>(out);
}